// round 11
// baseline (speedup 1.0000x reference)
#include <cuda_runtime.h>

#define BN 256
#define TN 512
#define CN 128
#define FN 128
#define NB 32

typedef unsigned long long ull;

__device__ float g_scratch[(size_t)BN * TN * FN];   // 64 MB scratch

__device__ __forceinline__ ull pk2(float lo, float hi) {
    ull r; asm("mov.b64 %0, {%1, %2};" : "=l"(r) : "f"(lo), "f"(hi)); return r;
}
__device__ __forceinline__ void upk2(ull v, float& lo, float& hi) {
    asm("mov.b64 {%0, %1}, %2;" : "=f"(lo), "=f"(hi) : "l"(v));
}
__device__ __forceinline__ ull fma2(ull a, ull b, ull c) {
    ull d; asm("fma.rn.f32x2 %0, %1, %2, %3;" : "=l"(d) : "l"(a), "l"(b), "l"(c)); return d;
}
__device__ __forceinline__ float wsum(float v) {
    #pragma unroll
    for (int o = 16; o; o >>= 1) v += __shfl_xor_sync(0xffffffffu, v, o);
    return v;
}

// ============================================================
// Conv1D: 512 threads, 4 rows x 4 cols per thread (2x occupancy of R10).
// Writes y to BOTH d_out (preserved Y) and scratch (working copy).
// ============================================================
__global__ __launch_bounds__(512, 2) void conv_kernel(
    const float* __restrict__ x, const float* __restrict__ W,
    const float* __restrict__ bias, float* __restrict__ y)
{
    __shared__ float Xs[64][33];
    __shared__ float Ws[32][128];

    const int b = blockIdx.y, t0 = blockIdx.x * 64, tid = threadIdx.x;
    const int lane = tid & 31, warp = tid >> 5;   // 16 warps
    const int cbase = lane * 4, rbase = warp * 4;

    ull acc2[4][2];
    #pragma unroll
    for (int i = 0; i < 4; i++) { acc2[i][0] = 0ull; acc2[i][1] = 0ull; }

    for (int k = 0; k < 3; k++) {
        for (int c0 = 0; c0 < CN; c0 += 32) {
            #pragma unroll
            for (int q = 0; q < 8; q++) {
                int e = tid + 512 * q, f = e & 127, cc = e >> 7;
                Ws[cc][f] = W[((size_t)(k * CN + c0 + cc)) * FN + f];
            }
            #pragma unroll
            for (int q = 0; q < 4; q++) {
                int e = tid + 512 * q, cc = e & 31, r = e >> 5;
                int t = t0 + r + k - 1;
                float v = 0.f;
                if (t >= 0 && t < TN) v = x[((size_t)b * TN + t) * CN + c0 + cc];
                Xs[r][cc] = v;
            }
            __syncthreads();
            #pragma unroll
            for (int cc = 0; cc < 32; cc++) {
                const ull* wp = (const ull*)&Ws[cc][cbase];
                ull w01 = wp[0], w23 = wp[1];
                #pragma unroll
                for (int i = 0; i < 4; i++) {
                    float xv = Xs[rbase + i][cc];
                    ull xx = pk2(xv, xv);
                    acc2[i][0] = fma2(xx, w01, acc2[i][0]);
                    acc2[i][1] = fma2(xx, w23, acc2[i][1]);
                }
            }
            __syncthreads();
        }
    }
    float b0 = bias[cbase], b1 = bias[cbase+1], b2 = bias[cbase+2], b3 = bias[cbase+3];
    #pragma unroll
    for (int i = 0; i < 4; i++) {
        int t = t0 + rbase + i;
        float4 o; float lo, hi;
        upk2(acc2[i][0], lo, hi); o.x = lo + b0; o.y = hi + b1;
        upk2(acc2[i][1], lo, hi); o.z = lo + b2; o.w = hi + b3;
        size_t off = ((size_t)b * TN + t) * FN + cbase;
        *(float4*)&y[off] = o;
        *(float4*)&g_scratch[off] = o;
    }
}

// ============================================================
// Fused geqrf + R^{-1} + (Q = Y * Rinv), one CTA per 512x128 matrix.
// ============================================================
#define VP(t,i)   Vp[(t) * 33 + (i)]
#define W2STRIDE  120
#define RGS       130   /* Rinv SMEM row stride (phase 3) */

template<int WT>
__device__ void block_apply(float* __restrict__ G, int o, int colbase,
                            const float* __restrict__ Vp, const float* __restrict__ Tp,
                            float* __restrict__ Wm, float* __restrict__ Wm2, int tid)
{
    const int lane = tid & 31, w = tid >> 5;
    constexpr int NU = WT / 32;
    constexpr int HW = WT / 2;
    constexpr int TU = 32 * HW;
    ull* Gs = (ull*)Wm2;

    // GEMM1: Wm[i][c] = sum_t V[t][i]*G[t][colbase+c]
    ull acc[NU];
    #pragma unroll
    for (int k = 0; k < NU; k++) acc[k] = 0ull;
    const int ntiles = (TN - o) >> 5;
    for (int tile = 0; tile < ntiles; tile++) {
        const int t0 = o + (tile << 5);
        #pragma unroll
        for (int u = tid; u < TU; u += 512) {
            int r = u / HW, c = u - r * HW;
            Gs[u] = *(const ull*)(G + (size_t)(t0 + r) * FN + colbase + 2 * c);
        }
        __syncthreads();
        #pragma unroll
        for (int r = 0; r < 32; r++) {
            float v = VP(t0 + r, lane);
            ull vv = pk2(v, v);
            const ull* g = Gs + r * HW + w * NU;
            #pragma unroll
            for (int k = 0; k < NU; k++) acc[k] = fma2(vv, g[k], acc[k]);
        }
        __syncthreads();
    }
    {
        ull* wout = (ull*)(Wm + lane * 96) + w * NU;
        #pragma unroll
        for (int k = 0; k < NU; k++) wout[k] = acc[k];
    }
    __syncthreads();

    // Tapply: Wm2 = -(T^T * Wm), group-10 padded
    {
        constexpr int NCG = WT / 8;
        for (int pos = tid; pos < 32 * NCG * 4; pos += 512) {
            int i = pos / (NCG * 4);
            int rem = pos - i * (NCG * 4);
            int cg = rem >> 2, k = rem & 3;
            int c = cg * 8 + 2 * k;
            ull a = 0ull;
            #pragma unroll
            for (int j = 0; j < 32; j++) {
                float tv = Tp[j * 33 + i];
                a = fma2(pk2(-tv, -tv), *(const ull*)(Wm + j * 96 + c), a);
            }
            *(ull*)(Wm2 + i * W2STRIDE + cg * 10 + 2 * k) = a;
        }
    }
    __syncthreads();

    // GEMM2: G += V * Wm2
    {
        constexpr int NCG = WT / 8;
        const int npos = ((TN - o) >> 2) * NCG;
        for (int pos = tid; pos < npos; pos += 512) {
            int tg = pos / NCG, cg = pos - tg * NCG;
            int t0 = o + (tg << 2);
            float* gp = G + (size_t)t0 * FN + colbase + cg * 8;
            ull a[4][4];
            #pragma unroll
            for (int r = 0; r < 4; r++) {
                ulonglong2 q0 = ((const ulonglong2*)(gp + r * FN))[0];
                ulonglong2 q1 = ((const ulonglong2*)(gp + r * FN))[1];
                a[r][0] = q0.x; a[r][1] = q0.y; a[r][2] = q1.x; a[r][3] = q1.y;
            }
            const float* vr0 = Vp + (size_t)t0 * 33;
            const float* vr1 = vr0 + 33;
            const float* vr2 = vr1 + 33;
            const float* vr3 = vr2 + 33;
            const float* w2base = Wm2 + cg * 10;
            #pragma unroll 4
            for (int i = 0; i < 32; i++) {
                const ull* wp = (const ull*)(w2base + i * W2STRIDE);
                ull w0 = wp[0], w1 = wp[1], w2 = wp[2], w3 = wp[3];
                float v0 = vr0[i], v1 = vr1[i], v2 = vr2[i], v3 = vr3[i];
                ull vv0 = pk2(v0, v0), vv1 = pk2(v1, v1);
                ull vv2 = pk2(v2, v2), vv3 = pk2(v3, v3);
                a[0][0] = fma2(vv0, w0, a[0][0]); a[0][1] = fma2(vv0, w1, a[0][1]);
                a[0][2] = fma2(vv0, w2, a[0][2]); a[0][3] = fma2(vv0, w3, a[0][3]);
                a[1][0] = fma2(vv1, w0, a[1][0]); a[1][1] = fma2(vv1, w1, a[1][1]);
                a[1][2] = fma2(vv1, w2, a[1][2]); a[1][3] = fma2(vv1, w3, a[1][3]);
                a[2][0] = fma2(vv2, w0, a[2][0]); a[2][1] = fma2(vv2, w1, a[2][1]);
                a[2][2] = fma2(vv2, w2, a[2][2]); a[2][3] = fma2(vv2, w3, a[2][3]);
                a[3][0] = fma2(vv3, w0, a[3][0]); a[3][1] = fma2(vv3, w1, a[3][1]);
                a[3][2] = fma2(vv3, w2, a[3][2]); a[3][3] = fma2(vv3, w3, a[3][3]);
            }
            #pragma unroll
            for (int r = 0; r < 4; r++) {
                ulonglong2 q0, q1;
                q0.x = a[r][0]; q0.y = a[r][1]; q1.x = a[r][2]; q1.y = a[r][3];
                ((ulonglong2*)(gp + r * FN))[0] = q0;
                ((ulonglong2*)(gp + r * FN))[1] = q1;
            }
        }
    }
    __syncthreads();
}

// Fused panel factorization: 2 barriers + 1 reduction chain per column.
__device__ void panel_factor(float* Vp, float* taus, float* betas,
                             float* wred, float* rowp, int o, int tid)
{
    const int lane = tid & 31, w = tid >> 5;
    const int c0 = w, c1 = w + 16;
    for (int i = 0; i < NB; i++) {
        const int prow = o + i;
        if (w == 0) rowp[lane] = VP(prow, lane);
        float p0 = 0.f, p1 = 0.f;
        for (int t = prow + lane; t < TN; t += 32) {
            float vi = VP(t, i);
            p0 += vi * VP(t, c0);
            p1 += vi * VP(t, c1);
        }
        p0 = wsum(p0); p1 = wsum(p1);
        if (lane == 0) { wred[c0] = p0; wred[c1] = p1; }
        __syncthreads();
        float alpha = rowp[i];
        float s2 = wred[i];
        float xn2 = s2 - alpha * alpha;
        float tau, sc, beta;
        if (xn2 <= 0.f) { tau = 0.f; sc = 0.f; beta = alpha; }
        else {
            beta = -copysignf(sqrtf(s2), alpha);
            tau  = (beta - alpha) / beta;
            sc   = 1.f / (alpha - beta);
        }
        if (tid == 0) { taus[i] = tau; betas[i] = beta; }
        float cjp  = rowp[lane];
        float coef = tau * (cjp + (wred[lane] - alpha * cjp) * sc);
        if (w == 0) {
            float nv = (lane == i) ? 1.f : cjp - coef;
            if (lane >= i) VP(prow, lane) = nv;
        }
        for (int t = prow + 1 + w; t < TN; t += 16) {
            float xt  = VP(t, i);
            float vt  = xt * sc;
            float cur = VP(t, lane);
            float nv  = (lane == i) ? vt : fmaf(-coef, vt, cur);
            if (lane >= i) VP(t, lane) = nv;
        }
        __syncthreads();
    }
}

__device__ void build_T(const float* Vp, float* B, float* Tp, const float* taus,
                        int o, int tid)
{
    const int lane = tid & 31, w = tid >> 5;
    for (int i = 1; i < NB; i++) {
        for (int j = w; j < i; j += 16) {
            float p = 0.f;
            for (int t = o + i + lane; t < TN; t += 32)
                p += VP(t, j) * VP(t, i);
            p = wsum(p);
            if (lane == 0) B[j * 32 + i] = p;
        }
    }
    __syncthreads();
    if (w == 0) {
        for (int i = 0; i < NB; i++) {
            float ti = taus[i];
            float a = 0.f;
            for (int k = 0; k < i; k++)
                a += Tp[lane * 33 + k] * B[k * 32 + i];
            float tv = (lane < i) ? -ti * a : (lane == i ? ti : 0.f);
            Tp[lane * 33 + i] = tv;
            __syncwarp();
        }
    }
    __syncthreads();
}

// SMEM (floats): Vp 16896 | Tp 1056 | Wm 3072 | Wm2 3840 | taus 32 | betas 32 | wred 32 | rowp 32 = 24992
// Phase 2 overlay: Rsm 128x130 (16640) | rd 128
// Phase 3 overlay: Rg 128x130 (16640)  | Ys 128x66 (8448) -> 25088
#define SM_FLOATS 25088
#define SM_BYTES  (SM_FLOATS * 4)

__global__ __launch_bounds__(512, 2) void qr_kernel(float* __restrict__ Yq)
{
    extern __shared__ float sm[];
    float* Vp    = sm;                 // 16896
    float* Tp    = Vp + 16896;         // 1056
    float* Wm    = Tp + 1056;          // 3072
    float* Wm2   = Wm + 3072;          // 3840 (also GEMM1 staging + build_T B)
    float* taus  = Wm2 + 3840;         // 32
    float* betas = taus + 32;          // 32
    float* wred  = betas + 32;         // 32
    float* rowp  = wred + 32;          // 32

    const int b = blockIdx.x;
    float* G = g_scratch + (size_t)b * TN * FN;
    float* Y = Yq + (size_t)b * TN * FN;
    const int tid = threadIdx.x;
    const int lane = tid & 31, w = tid >> 5;

    // ---------------- geqrf (blocked, trailing only) ----------------
    for (int p = 0; p < 4; p++) {
        const int o = p * 32;
        for (int t = o + w; t < TN; t += 16)
            VP(t, lane) = G[(size_t)t * FN + o + lane];
        __syncthreads();
        panel_factor(Vp, taus, betas, wred, rowp, o, tid);
        // write this panel's 32x32 R block to scratch (zeros below diag)
        for (int pos = tid; pos < 32 * 32; pos += 512) {
            int r = pos >> 5, i = pos & 31;
            float val = (r < i) ? VP(o + r, i) : (r == i ? betas[i] : 0.f);
            G[(size_t)(o + r) * FN + o + i] = val;
        }
        __syncthreads();
        if (p < 3) {
            for (int pos = tid; pos < 32 * 32; pos += 512) {
                int i = pos >> 5, r = pos & 31;
                if (r < i) VP(o + r, i) = 0.f;
            }
            __syncthreads();
            build_T(Vp, Wm2, Tp, taus, o, tid);
            if (p == 0)      block_apply<96>(G, 0,  32, Vp, Tp, Wm, Wm2, tid);
            else if (p == 1) block_apply<64>(G, 32, 64, Vp, Tp, Wm, Wm2, tid);
            else             block_apply<32>(G, 64, 96, Vp, Tp, Wm, Wm2, tid);
        }
    }
    __syncthreads();

    // ---------------- R^{-1} with 8-column ILP per warp ----------------
    float* Rsm = sm;             // 128 x 130 (overlays Vp)
    float* rd  = sm + 16640;     // 128 reciprocals
    for (int e = tid; e < 128 * 128; e += 512) {
        int r = e >> 7, c = e & 127;
        Rsm[r * 130 + c] = G[(size_t)r * FN + c];
    }
    __syncthreads();
    if (tid < 128) rd[tid] = 1.f / Rsm[tid * 130 + tid];
    __syncthreads();

    float xr[8][4];   // warp w owns columns c = w + 16m
    #pragma unroll
    for (int m = 0; m < 8; m++) {
        #pragma unroll
        for (int q = 0; q < 4; q++) xr[m][q] = 0.f;
        int c = w + (m << 4);
        float dv = rd[c];
        if ((c & 31) == lane) {
            int q = c >> 5;
            if (q == 0) xr[m][0] = dv; else if (q == 1) xr[m][1] = dv;
            else if (q == 2) xr[m][2] = dv; else xr[m][3] = dv;
        }
    }
    for (int k = 126; k >= 0; k--) {
        const float* Rk = Rsm + k * 130;
        float r0 = Rk[lane], r1 = Rk[lane + 32], r2 = Rk[lane + 64], r3 = Rk[lane + 96];
        float rk = rd[k];
        int qk = k >> 5, lk = k & 31;
        #pragma unroll
        for (int m = 0; m < 8; m++) {
            int c = w + (m << 4);
            if (c > k) {
                float s = r0 * xr[m][0] + r1 * xr[m][1] + r2 * xr[m][2] + r3 * xr[m][3];
                s = wsum(s);
                float xk = -s * rk;
                if (lk == lane) {
                    if (qk == 0) xr[m][0] = xk; else if (qk == 1) xr[m][1] = xk;
                    else if (qk == 2) xr[m][2] = xk; else xr[m][3] = xk;
                }
            }
        }
    }
    __syncthreads();   // all solve reads of Rsm complete

    // ---------------- Rinv -> SMEM (stride-130, reads are warp-uniform) ----------------
    float* Rg = sm;              // 128 x 130 (in place of Rsm)
    float* Ys = sm + 16640;      // 128 x 66
    #pragma unroll
    for (int m = 0; m < 8; m++) {
        int c = w + (m << 4);
        float* dst = Rg + c;
        dst[(size_t)lane * RGS]        = xr[m][0];   // rows > c are 0 in xr
        dst[(size_t)(lane + 32) * RGS] = xr[m][1];
        dst[(size_t)(lane + 64) * RGS] = xr[m][2];
        dst[(size_t)(lane + 96) * RGS] = xr[m][3];
    }
    __syncthreads();

    // ---------------- Q = Y * Rinv (8 tiles of 64 rows, 2 rows/thread) ----------------
    // Warp w handles col groups A = 4w and B = 124-4w (balanced k-work).
    const int cA = 4 * w, cB = 124 - 4 * w;
    const int kmaxA = cA + 4, kmaxB = cB + 4;
    const float* RgA = Rg + cA;
    const float* RgB = Rg + cB;

    for (int tile = 0; tile < 8; tile++) {
        const int t0 = tile * 64;
        // stage Y tile transposed: Ys[k][r], r in [0,64)
        #pragma unroll
        for (int e = tid; e < 64 * 32; e += 512) {
            int r = e >> 5, g4 = e & 31;
            float4 v = *(const float4*)(Y + (size_t)(t0 + r) * FN + g4 * 4);
            float* dst = Ys + (g4 * 4) * 66 + r;
            dst[0] = v.x; dst[66] = v.y; dst[132] = v.z; dst[198] = v.w;
        }
        __syncthreads();

        ull aA0 = 0ull, aA1 = 0ull, aB0 = 0ull, aB1 = 0ull;   // row lane
        ull bA0 = 0ull, bA1 = 0ull, bB0 = 0ull, bB1 = 0ull;   // row lane+32
        const float* yb0 = Ys + lane;
        const float* yb1 = Ys + lane + 32;
        int k = 0;
        for (; k < kmaxA; k++) {
            float y0 = yb0[k * 66], y1 = yb1[k * 66];
            ull v0 = pk2(y0, y0), v1 = pk2(y1, y1);
            const ull* wa = (const ull*)(RgA + k * RGS);
            const ull* wb = (const ull*)(RgB + k * RGS);
            ull wa0 = wa[0], wa1 = wa[1], wb0 = wb[0], wb1 = wb[1];
            aA0 = fma2(v0, wa0, aA0); aA1 = fma2(v0, wa1, aA1);
            aB0 = fma2(v0, wb0, aB0); aB1 = fma2(v0, wb1, aB1);
            bA0 = fma2(v1, wa0, bA0); bA1 = fma2(v1, wa1, bA1);
            bB0 = fma2(v1, wb0, bB0); bB1 = fma2(v1, wb1, bB1);
        }
        for (; k < kmaxB; k++) {
            float y0 = yb0[k * 66], y1 = yb1[k * 66];
            ull v0 = pk2(y0, y0), v1 = pk2(y1, y1);
            const ull* wb = (const ull*)(RgB + k * RGS);
            ull wb0 = wb[0], wb1 = wb[1];
            aB0 = fma2(v0, wb0, aB0); aB1 = fma2(v0, wb1, aB1);
            bB0 = fma2(v1, wb0, bB0); bB1 = fma2(v1, wb1, bB1);
        }
        __syncthreads();   // done reading Ys before restage

        float* orow0 = Y + (size_t)(t0 + lane) * FN;
        float* orow1 = Y + (size_t)(t0 + lane + 32) * FN;
        ulonglong2 q;
        q.x = aA0; q.y = aA1; *(ulonglong2*)(orow0 + cA) = q;
        q.x = aB0; q.y = aB1; *(ulonglong2*)(orow0 + cB) = q;
        q.x = bA0; q.y = bA1; *(ulonglong2*)(orow1 + cA) = q;
        q.x = bB0; q.y = bB1; *(ulonglong2*)(orow1 + cB) = q;
    }
}

// ============================================================
extern "C" void kernel_launch(void* const* d_in, const int* in_sizes, int n_in,
                              void* d_out, int out_size)
{
    const float* x    = (const float*)d_in[0];
    const float* W    = (const float*)d_in[1];
    const float* bias = (const float*)d_in[2];
    float* out = (float*)d_out;

    cudaFuncSetAttribute(qr_kernel, cudaFuncAttributeMaxDynamicSharedMemorySize, SM_BYTES);

    dim3 cgrid(TN / 64, BN);
    conv_kernel<<<cgrid, 512>>>(x, W, bias, out);   // Y -> d_out AND scratch
    qr_kernel<<<BN, 512, SM_BYTES>>>(out);          // geqrf + Rinv + Q, in-place
}

// round 12
// speedup vs baseline: 1.0681x; 1.0681x over previous
#include <cuda_runtime.h>

#define BN 256
#define TN 512
#define CN 128
#define FN 128
#define NB 32
#define VS 34      /* Vp row stride (even -> 8B-aligned col pairs) */

typedef unsigned long long ull;

__device__ float g_scratch[(size_t)BN * TN * FN];   // 64 MB scratch

__device__ __forceinline__ ull pk2(float lo, float hi) {
    ull r; asm("mov.b64 %0, {%1, %2};" : "=l"(r) : "f"(lo), "f"(hi)); return r;
}
__device__ __forceinline__ void upk2(ull v, float& lo, float& hi) {
    asm("mov.b64 {%0, %1}, %2;" : "=f"(lo), "=f"(hi) : "l"(v));
}
__device__ __forceinline__ ull fma2(ull a, ull b, ull c) {
    ull d; asm("fma.rn.f32x2 %0, %1, %2, %3;" : "=l"(d) : "l"(a), "l"(b), "l"(c)); return d;
}
__device__ __forceinline__ ull mul2(ull a, ull b) {
    ull d; asm("mul.rn.f32x2 %0, %1, %2;" : "=l"(d) : "l"(a), "l"(b)); return d;
}
__device__ __forceinline__ float wsum(float v) {
    #pragma unroll
    for (int o = 16; o; o >>= 1) v += __shfl_xor_sync(0xffffffffu, v, o);
    return v;
}

// ============================================================
// Conv1D (256 threads, 8 rows x 4 cols/thread — proven fastest variant).
// Writes y to BOTH d_out (preserved Y) and scratch (working copy).
// ============================================================
__global__ __launch_bounds__(256) void conv_kernel(
    const float* __restrict__ x, const float* __restrict__ W,
    const float* __restrict__ bias, float* __restrict__ y)
{
    __shared__ float Xs[64][33];
    __shared__ float Ws[32][128];

    const int b = blockIdx.y, t0 = blockIdx.x * 64, tid = threadIdx.x;
    const int lane = tid & 31, warp = tid >> 5;
    const int cbase = lane * 4, rbase = warp * 8;

    ull acc2[8][2];
    #pragma unroll
    for (int i = 0; i < 8; i++) { acc2[i][0] = 0ull; acc2[i][1] = 0ull; }

    for (int k = 0; k < 3; k++) {
        for (int c0 = 0; c0 < CN; c0 += 32) {
            #pragma unroll
            for (int q = 0; q < 16; q++) {
                int e = tid + 256 * q, f = e & 127, cc = e >> 7;
                Ws[cc][f] = W[((size_t)(k * CN + c0 + cc)) * FN + f];
            }
            #pragma unroll
            for (int q = 0; q < 8; q++) {
                int e = tid + 256 * q, cc = e & 31, r = e >> 5;
                int t = t0 + r + k - 1;
                float v = 0.f;
                if (t >= 0 && t < TN) v = x[((size_t)b * TN + t) * CN + c0 + cc];
                Xs[r][cc] = v;
            }
            __syncthreads();
            #pragma unroll
            for (int cc = 0; cc < 32; cc++) {
                const ull* wp = (const ull*)&Ws[cc][cbase];
                ull w01 = wp[0], w23 = wp[1];
                #pragma unroll
                for (int i = 0; i < 8; i++) {
                    float xv = Xs[rbase + i][cc];
                    ull xx = pk2(xv, xv);
                    acc2[i][0] = fma2(xx, w01, acc2[i][0]);
                    acc2[i][1] = fma2(xx, w23, acc2[i][1]);
                }
            }
            __syncthreads();
        }
    }
    float b0 = bias[cbase], b1 = bias[cbase+1], b2 = bias[cbase+2], b3 = bias[cbase+3];
    #pragma unroll
    for (int i = 0; i < 8; i++) {
        int t = t0 + rbase + i;
        float4 o; float lo, hi;
        upk2(acc2[i][0], lo, hi); o.x = lo + b0; o.y = hi + b1;
        upk2(acc2[i][1], lo, hi); o.z = lo + b2; o.w = hi + b3;
        size_t off = ((size_t)b * TN + t) * FN + cbase;
        *(float4*)&y[off] = o;
        *(float4*)&g_scratch[off] = o;
    }
}

// ============================================================
// Fused geqrf + R^{-1} + (Q = Y * Rinv), one CTA per 512x128 matrix.
// ============================================================
#define VP(t,i)   Vp[(t) * VS + (i)]
#define W2STRIDE  120
#define RGS       130   /* Rinv SMEM row stride (phase 3) */

template<int WT>
__device__ void block_apply(float* __restrict__ G, int o, int colbase,
                            const float* __restrict__ Vp, const float* __restrict__ Tp,
                            float* __restrict__ Wm, float* __restrict__ Wm2, int tid)
{
    const int lane = tid & 31, w = tid >> 5;
    constexpr int NU = WT / 32;
    constexpr int HW = WT / 2;
    constexpr int TU = 32 * HW;
    ull* Gs = (ull*)Wm2;

    // GEMM1: Wm[i][c] = sum_t V[t][i]*G[t][colbase+c]
    ull acc[NU];
    #pragma unroll
    for (int k = 0; k < NU; k++) acc[k] = 0ull;
    const int ntiles = (TN - o) >> 5;
    for (int tile = 0; tile < ntiles; tile++) {
        const int t0 = o + (tile << 5);
        #pragma unroll
        for (int u = tid; u < TU; u += 512) {
            int r = u / HW, c = u - r * HW;
            Gs[u] = *(const ull*)(G + (size_t)(t0 + r) * FN + colbase + 2 * c);
        }
        __syncthreads();
        #pragma unroll
        for (int r = 0; r < 32; r++) {
            float v = VP(t0 + r, lane);
            ull vv = pk2(v, v);
            const ull* g = Gs + r * HW + w * NU;
            #pragma unroll
            for (int k = 0; k < NU; k++) acc[k] = fma2(vv, g[k], acc[k]);
        }
        __syncthreads();
    }
    {
        ull* wout = (ull*)(Wm + lane * 96) + w * NU;
        #pragma unroll
        for (int k = 0; k < NU; k++) wout[k] = acc[k];
    }
    __syncthreads();

    // Tapply: Wm2 = -(T^T * Wm), group-10 padded
    {
        constexpr int NCG = WT / 8;
        for (int pos = tid; pos < 32 * NCG * 4; pos += 512) {
            int i = pos / (NCG * 4);
            int rem = pos - i * (NCG * 4);
            int cg = rem >> 2, k = rem & 3;
            int c = cg * 8 + 2 * k;
            ull a = 0ull;
            #pragma unroll
            for (int j = 0; j < 32; j++) {
                float tv = Tp[j * 33 + i];
                a = fma2(pk2(-tv, -tv), *(const ull*)(Wm + j * 96 + c), a);
            }
            *(ull*)(Wm2 + i * W2STRIDE + cg * 10 + 2 * k) = a;
        }
    }
    __syncthreads();

    // GEMM2: G += V * Wm2
    {
        constexpr int NCG = WT / 8;
        const int npos = ((TN - o) >> 2) * NCG;
        for (int pos = tid; pos < npos; pos += 512) {
            int tg = pos / NCG, cg = pos - tg * NCG;
            int t0 = o + (tg << 2);
            float* gp = G + (size_t)t0 * FN + colbase + cg * 8;
            ull a[4][4];
            #pragma unroll
            for (int r = 0; r < 4; r++) {
                ulonglong2 q0 = ((const ulonglong2*)(gp + r * FN))[0];
                ulonglong2 q1 = ((const ulonglong2*)(gp + r * FN))[1];
                a[r][0] = q0.x; a[r][1] = q0.y; a[r][2] = q1.x; a[r][3] = q1.y;
            }
            const float* vr0 = Vp + (size_t)t0 * VS;
            const float* vr1 = vr0 + VS;
            const float* vr2 = vr1 + VS;
            const float* vr3 = vr2 + VS;
            const float* w2base = Wm2 + cg * 10;
            #pragma unroll 4
            for (int i = 0; i < 32; i++) {
                const ull* wp = (const ull*)(w2base + i * W2STRIDE);
                ull w0 = wp[0], w1 = wp[1], w2 = wp[2], w3 = wp[3];
                float v0 = vr0[i], v1 = vr1[i], v2 = vr2[i], v3 = vr3[i];
                ull vv0 = pk2(v0, v0), vv1 = pk2(v1, v1);
                ull vv2 = pk2(v2, v2), vv3 = pk2(v3, v3);
                a[0][0] = fma2(vv0, w0, a[0][0]); a[0][1] = fma2(vv0, w1, a[0][1]);
                a[0][2] = fma2(vv0, w2, a[0][2]); a[0][3] = fma2(vv0, w3, a[0][3]);
                a[1][0] = fma2(vv1, w0, a[1][0]); a[1][1] = fma2(vv1, w1, a[1][1]);
                a[1][2] = fma2(vv1, w2, a[1][2]); a[1][3] = fma2(vv1, w3, a[1][3]);
                a[2][0] = fma2(vv2, w0, a[2][0]); a[2][1] = fma2(vv2, w1, a[2][1]);
                a[2][2] = fma2(vv2, w2, a[2][2]); a[2][3] = fma2(vv2, w3, a[2][3]);
                a[3][0] = fma2(vv3, w0, a[3][0]); a[3][1] = fma2(vv3, w1, a[3][1]);
                a[3][2] = fma2(vv3, w2, a[3][2]); a[3][3] = fma2(vv3, w3, a[3][3]);
            }
            #pragma unroll
            for (int r = 0; r < 4; r++) {
                ulonglong2 q0, q1;
                q0.x = a[r][0]; q0.y = a[r][1]; q1.x = a[r][2]; q1.y = a[r][3];
                ((ulonglong2*)(gp + r * FN))[0] = q0;
                ((ulonglong2*)(gp + r * FN))[1] = q1;
            }
        }
    }
    __syncthreads();
}

// Packed panel factorization: 2 barriers/column; phase A and C use f32x2.
__device__ void panel_factor(float* Vp, float* taus, float* betas,
                             float* wred, float* rowp, int o, int tid)
{
    const int lane = tid & 31, w = tid >> 5;
    const int ca = 2 * w;                    // phase A: warp w owns cols (2w, 2w+1)
    const int half = lane >> 4;              // phase C: 2 rows/warp-iter
    const int cl2 = (lane & 15) * 2;         // phase C: lane owns cols (cl2, cl2+1)

    for (int i = 0; i < NB; i++) {
        const int prow = o + i;
        if (w == 0) rowp[lane] = VP(prow, lane);
        // ---- Phase A: packed dots s_j = sum_{t>=prow} x_t * c_j[t] ----
        ull acc = 0ull;
        #pragma unroll 2
        for (int t = prow + lane; t < TN; t += 32) {
            float vi = VP(t, i);
            ull pr = *(const ull*)&VP(t, ca);
            acc = fma2(pk2(vi, vi), pr, acc);
        }
        float p0, p1; upk2(acc, p0, p1);
        p0 = wsum(p0); p1 = wsum(p1);
        if (lane == 0) { wred[ca] = p0; wred[ca + 1] = p1; }
        __syncthreads();
        // redundant scalar compute (all threads)
        float alpha = rowp[i];
        float s2 = wred[i];
        float xn2 = s2 - alpha * alpha;
        float tau, sc, beta;
        if (xn2 <= 0.f) { tau = 0.f; sc = 0.f; beta = alpha; }
        else {
            beta = -copysignf(sqrtf(s2), alpha);
            tau  = (beta - alpha) / beta;
            sc   = 1.f / (alpha - beta);
        }
        if (tid == 0) { taus[i] = tau; betas[i] = beta; }
        // ---- row prow (scalar, warp 0) ----
        if (w == 0) {
            float cjp  = rowp[lane];
            float coef = tau * (cjp + (wred[lane] - alpha * cjp) * sc);
            float nv = (lane == i) ? 1.f : cjp - coef;
            if (lane >= i) VP(prow, lane) = nv;
        }
        // ---- Phase C: packed rank-1 update, 2 cols/lane, 2 rows/warp-iter ----
        // per-column affine: new = a*vt + b*cur, loop-invariant (a,b) per lane
        {
            int c0 = cl2, c1 = cl2 + 1;
            float cj0 = rowp[c0], cj1 = rowp[c1];
            float cf0 = tau * (cj0 + (wred[c0] - alpha * cj0) * sc);
            float cf1 = tau * (cj1 + (wred[c1] - alpha * cj1) * sc);
            float a0 = (c0 > i) ? -cf0 : (c0 == i ? 1.f : 0.f);
            float b0 = (c0 == i) ? 0.f : 1.f;
            float a1 = (c1 > i) ? -cf1 : (c1 == i ? 1.f : 0.f);
            float b1 = (c1 == i) ? 0.f : 1.f;
            ull ap = pk2(a0, a1), bp = pk2(b0, b1);
            for (int t = prow + 1 + 2 * w + half; t < TN; t += 32) {
                float xt = VP(t, i);
                float vt = xt * sc;
                ull cur = *(const ull*)&VP(t, cl2);
                ull nv  = fma2(pk2(vt, vt), ap, mul2(bp, cur));
                *(ull*)&VP(t, cl2) = nv;
            }
        }
        __syncthreads();
    }
}

__device__ void build_T(const float* Vp, float* B, float* Tp, const float* taus,
                        int o, int tid)
{
    const int lane = tid & 31, w = tid >> 5;
    for (int i = 1; i < NB; i++) {
        for (int j = w; j < i; j += 16) {
            float p = 0.f;
            for (int t = o + i + lane; t < TN; t += 32)
                p += VP(t, j) * VP(t, i);
            p = wsum(p);
            if (lane == 0) B[j * 32 + i] = p;
        }
    }
    __syncthreads();
    if (w == 0) {
        for (int i = 0; i < NB; i++) {
            float ti = taus[i];
            float a = 0.f;
            for (int k = 0; k < i; k++)
                a += Tp[lane * 33 + k] * B[k * 32 + i];
            float tv = (lane < i) ? -ti * a : (lane == i ? ti : 0.f);
            Tp[lane * 33 + i] = tv;
            __syncwarp();
        }
    }
    __syncthreads();
}

// SMEM (floats): Vp 17408 | Tp 1056 | Wm 3072 | Wm2 3840 | taus 32 | betas 32 | wred 32 | rowp 32 = 25504
// Phase 2 overlay: Rsm 128x130 (16640) | rd 128  -> 16768
// Phase 3 overlay: Rg 128x130 (16640)  | Ys 128x66 (8448) -> 25088
#define SM_FLOATS 25504
#define SM_BYTES  (SM_FLOATS * 4)

__global__ __launch_bounds__(512, 2) void qr_kernel(float* __restrict__ Yq)
{
    extern __shared__ float sm[];
    float* Vp    = sm;                 // 17408
    float* Tp    = Vp + 17408;         // 1056
    float* Wm    = Tp + 1056;          // 3072
    float* Wm2   = Wm + 3072;          // 3840 (also GEMM1 staging + build_T B)
    float* taus  = Wm2 + 3840;         // 32
    float* betas = taus + 32;          // 32
    float* wred  = betas + 32;         // 32
    float* rowp  = wred + 32;          // 32

    const int b = blockIdx.x;
    float* G = g_scratch + (size_t)b * TN * FN;
    float* Y = Yq + (size_t)b * TN * FN;
    const int tid = threadIdx.x;
    const int lane = tid & 31, w = tid >> 5;

    // ---------------- geqrf (blocked, trailing only) ----------------
    for (int p = 0; p < 4; p++) {
        const int o = p * 32;
        for (int t = o + w; t < TN; t += 16)
            VP(t, lane) = G[(size_t)t * FN + o + lane];
        __syncthreads();
        panel_factor(Vp, taus, betas, wred, rowp, o, tid);
        // write this panel's 32x32 R block to scratch (zeros below diag)
        for (int pos = tid; pos < 32 * 32; pos += 512) {
            int r = pos >> 5, i = pos & 31;
            float val = (r < i) ? VP(o + r, i) : (r == i ? betas[i] : 0.f);
            G[(size_t)(o + r) * FN + o + i] = val;
        }
        __syncthreads();
        if (p < 3) {
            for (int pos = tid; pos < 32 * 32; pos += 512) {
                int i = pos >> 5, r = pos & 31;
                if (r < i) VP(o + r, i) = 0.f;
            }
            __syncthreads();
            build_T(Vp, Wm2, Tp, taus, o, tid);
            if (p == 0)      block_apply<96>(G, 0,  32, Vp, Tp, Wm, Wm2, tid);
            else if (p == 1) block_apply<64>(G, 32, 64, Vp, Tp, Wm, Wm2, tid);
            else             block_apply<32>(G, 64, 96, Vp, Tp, Wm, Wm2, tid);
        }
    }
    __syncthreads();

    // ---------------- R^{-1} with 8-column ILP per warp ----------------
    float* Rsm = sm;             // 128 x 130 (overlays Vp)
    float* rd  = sm + 16640;     // 128 reciprocals
    for (int e = tid; e < 128 * 128; e += 512) {
        int r = e >> 7, c = e & 127;
        Rsm[r * 130 + c] = G[(size_t)r * FN + c];
    }
    __syncthreads();
    if (tid < 128) rd[tid] = 1.f / Rsm[tid * 130 + tid];
    __syncthreads();

    float xr[8][4];   // warp w owns columns c = w + 16m
    #pragma unroll
    for (int m = 0; m < 8; m++) {
        #pragma unroll
        for (int q = 0; q < 4; q++) xr[m][q] = 0.f;
        int c = w + (m << 4);
        float dv = rd[c];
        if ((c & 31) == lane) {
            int q = c >> 5;
            if (q == 0) xr[m][0] = dv; else if (q == 1) xr[m][1] = dv;
            else if (q == 2) xr[m][2] = dv; else xr[m][3] = dv;
        }
    }
    for (int k = 126; k >= 0; k--) {
        const float* Rk = Rsm + k * 130;
        float r0 = Rk[lane], r1 = Rk[lane + 32], r2 = Rk[lane + 64], r3 = Rk[lane + 96];
        float rk = rd[k];
        int qk = k >> 5, lk = k & 31;
        #pragma unroll
        for (int m = 0; m < 8; m++) {
            int c = w + (m << 4);
            if (c > k) {
                float s = r0 * xr[m][0] + r1 * xr[m][1] + r2 * xr[m][2] + r3 * xr[m][3];
                s = wsum(s);
                float xk = -s * rk;
                if (lk == lane) {
                    if (qk == 0) xr[m][0] = xk; else if (qk == 1) xr[m][1] = xk;
                    else if (qk == 2) xr[m][2] = xk; else xr[m][3] = xk;
                }
            }
        }
    }
    __syncthreads();   // all solve reads of Rsm complete

    // ---------------- Rinv -> SMEM (stride-130, reads are warp-uniform) ----------------
    float* Rg = sm;              // 128 x 130 (in place of Rsm)
    float* Ys = sm + 16640;      // 128 x 66
    #pragma unroll
    for (int m = 0; m < 8; m++) {
        int c = w + (m << 4);
        float* dst = Rg + c;
        dst[(size_t)lane * RGS]        = xr[m][0];   // rows > c are 0 in xr
        dst[(size_t)(lane + 32) * RGS] = xr[m][1];
        dst[(size_t)(lane + 64) * RGS] = xr[m][2];
        dst[(size_t)(lane + 96) * RGS] = xr[m][3];
    }
    __syncthreads();

    // ---------------- Q = Y * Rinv (8 tiles of 64 rows, 2 rows/thread) ----------------
    const int cA = 4 * w, cB = 124 - 4 * w;
    const int kmaxA = cA + 4, kmaxB = cB + 4;
    const float* RgA = Rg + cA;
    const float* RgB = Rg + cB;

    for (int tile = 0; tile < 8; tile++) {
        const int t0 = tile * 64;
        #pragma unroll
        for (int e = tid; e < 64 * 32; e += 512) {
            int r = e >> 5, g4 = e & 31;
            float4 v = *(const float4*)(Y + (size_t)(t0 + r) * FN + g4 * 4);
            float* dst = Ys + (g4 * 4) * 66 + r;
            dst[0] = v.x; dst[66] = v.y; dst[132] = v.z; dst[198] = v.w;
        }
        __syncthreads();

        ull aA0 = 0ull, aA1 = 0ull, aB0 = 0ull, aB1 = 0ull;   // row lane
        ull bA0 = 0ull, bA1 = 0ull, bB0 = 0ull, bB1 = 0ull;   // row lane+32
        const float* yb0 = Ys + lane;
        const float* yb1 = Ys + lane + 32;
        int k = 0;
        for (; k < kmaxA; k++) {
            float y0 = yb0[k * 66], y1 = yb1[k * 66];
            ull v0 = pk2(y0, y0), v1 = pk2(y1, y1);
            const ull* wa = (const ull*)(RgA + k * RGS);
            const ull* wb = (const ull*)(RgB + k * RGS);
            ull wa0 = wa[0], wa1 = wa[1], wb0 = wb[0], wb1 = wb[1];
            aA0 = fma2(v0, wa0, aA0); aA1 = fma2(v0, wa1, aA1);
            aB0 = fma2(v0, wb0, aB0); aB1 = fma2(v0, wb1, aB1);
            bA0 = fma2(v1, wa0, bA0); bA1 = fma2(v1, wa1, bA1);
            bB0 = fma2(v1, wb0, bB0); bB1 = fma2(v1, wb1, bB1);
        }
        for (; k < kmaxB; k++) {
            float y0 = yb0[k * 66], y1 = yb1[k * 66];
            ull v0 = pk2(y0, y0), v1 = pk2(y1, y1);
            const ull* wb = (const ull*)(RgB + k * RGS);
            ull wb0 = wb[0], wb1 = wb[1];
            aB0 = fma2(v0, wb0, aB0); aB1 = fma2(v0, wb1, aB1);
            bB0 = fma2(v1, wb0, bB0); bB1 = fma2(v1, wb1, bB1);
        }
        __syncthreads();   // done reading Ys before restage

        float* orow0 = Y + (size_t)(t0 + lane) * FN;
        float* orow1 = Y + (size_t)(t0 + lane + 32) * FN;
        ulonglong2 q;
        q.x = aA0; q.y = aA1; *(ulonglong2*)(orow0 + cA) = q;
        q.x = aB0; q.y = aB1; *(ulonglong2*)(orow0 + cB) = q;
        q.x = bA0; q.y = bA1; *(ulonglong2*)(orow1 + cA) = q;
        q.x = bB0; q.y = bB1; *(ulonglong2*)(orow1 + cB) = q;
    }
}

// ============================================================
extern "C" void kernel_launch(void* const* d_in, const int* in_sizes, int n_in,
                              void* d_out, int out_size)
{
    const float* x    = (const float*)d_in[0];
    const float* W    = (const float*)d_in[1];
    const float* bias = (const float*)d_in[2];
    float* out = (float*)d_out;

    cudaFuncSetAttribute(qr_kernel, cudaFuncAttributeMaxDynamicSharedMemorySize, SM_BYTES);

    dim3 cgrid(TN / 64, BN);
    conv_kernel<<<cgrid, 256>>>(x, W, bias, out);   // Y -> d_out AND scratch
    qr_kernel<<<BN, 512, SM_BYTES>>>(out);          // geqrf + Rinv + Q, in-place
}